// round 14
// baseline (speedup 1.0000x reference)
#include <cuda_runtime.h>
#include <math.h>

constexpr int B = 8, N1 = 64, N2 = 512, D = 128, NL = 3, H = 128, NT = 7;

// ---------------- scratch (static device memory) ----------------------------
constexpr size_t SZ_H1   = (size_t)B * N1 * D;
constexpr size_t SZ_H2   = (size_t)B * N2 * D;
constexpr size_t SZ_ATT1 = (size_t)B * N1 * N1;
constexpr size_t SZ_ATT2 = (size_t)B * N2 * N2;
constexpr size_t SZ_U1   = (size_t)B * N1 * NT * H;
constexpr size_t SZ_U2   = (size_t)B * N2 * NT * H;
constexpr size_t SZ_EP   = (size_t)B * NT * N1;
constexpr size_t SZ_ST1  = (size_t)B * N1;
constexpr size_t SZ_ST2  = (size_t)B * N2;
constexpr size_t SZ_MP2  = (size_t)B * 8 * N2;   // per-tile stat partials
constexpr size_t SZ_MP1  = (size_t)B * 1 * N1;

constexpr size_t OFF_H1A  = 0;
constexpr size_t OFF_H1B  = OFF_H1A  + SZ_H1;
constexpr size_t OFF_H2A  = OFF_H1B  + SZ_H1;
constexpr size_t OFF_H2B  = OFF_H2A  + SZ_H2;
constexpr size_t OFF_T1   = OFF_H2B  + SZ_H2;
constexpr size_t OFF_TA1  = OFF_T1   + SZ_H1;
constexpr size_t OFF_T2   = OFF_TA1  + SZ_H1;
constexpr size_t OFF_TA2  = OFF_T2   + SZ_H2;
constexpr size_t OFF_E1   = OFF_TA2  + SZ_H2;
constexpr size_t OFF_E2   = OFF_E1   + SZ_ATT1;
constexpr size_t OFF_M1   = OFF_E2   + SZ_ATT2;
constexpr size_t OFF_S1   = OFF_M1   + SZ_ST1;
constexpr size_t OFF_M2   = OFF_S1   + SZ_ST1;
constexpr size_t OFF_S2   = OFF_M2   + SZ_ST2;
constexpr size_t OFF_MP2  = OFF_S2   + SZ_ST2;
constexpr size_t OFF_SP2  = OFF_MP2  + SZ_MP2;
constexpr size_t OFF_MP1  = OFF_SP2  + SZ_MP2;
constexpr size_t OFF_SP1  = OFF_MP1  + SZ_MP1;
constexpr size_t OFF_U1A  = OFF_SP1  + SZ_MP1;
constexpr size_t OFF_U1B  = OFF_U1A  + SZ_U1;
constexpr size_t OFF_U2A  = OFF_U1B  + SZ_U1;
constexpr size_t OFF_U2B  = OFF_U2A  + SZ_U2;
constexpr size_t OFF_EP   = OFF_U2B  + SZ_U2;
constexpr size_t SCRATCH_TOTAL = OFF_EP + SZ_EP;

__device__ float g_scratch[SCRATCH_TOTAL];

__constant__ float c_bconstraint[NT] = {1.159f, 0.448f, 0.927f, 0.902f, 0.349f, 0.789f, 0.198f};

__device__ __forceinline__ float sigmoidf(float x) { return 1.f / (1.f + expf(-x)); }

// ---------------- packed fp32x2 helpers (sm_103a dual-fp32 pipe) ------------
__device__ __forceinline__ unsigned long long pack2(float lo, float hi) {
    unsigned long long r;
    asm("mov.b64 %0, {%1,%2};" : "=l"(r) : "f"(lo), "f"(hi));
    return r;
}
__device__ __forceinline__ void unpack2(unsigned long long v, float& lo, float& hi) {
    asm("mov.b64 {%0,%1}, %2;" : "=f"(lo), "=f"(hi) : "l"(v));
}
__device__ __forceinline__ void fma2(unsigned long long& d, unsigned long long a,
                                     unsigned long long b) {
    asm("fma.rn.f32x2 %0, %1, %2, %0;" : "+l"(d) : "l"(a), "l"(b));
}
__device__ __forceinline__ unsigned long long lds2(const float* p) {
    return *reinterpret_cast<const unsigned long long*>(p);
}

// ---------------- embedding (both graphs, one launch) ------------------------
template <int TM>
__global__ void k_embed(const float* __restrict__ x1, const float* __restrict__ x2,
                        const float* __restrict__ W,
                        float* __restrict__ o1, float* __restrict__ o2) {
    constexpr int T1 = (B * N1) / TM;
    int blk = blockIdx.x;
    const float* x; float* out; int r0;
    if (blk < T1) { x = x1; out = o1; r0 = blk * TM; }
    else          { x = x2; out = o2; r0 = (blk - T1) * TM; }
    int t = threadIdx.x;
    __shared__ float xs[TM][56];
    for (int idx = t; idx < TM * 56; idx += 128) {
        int m = idx / 56, d = idx % 56;
        xs[m][d] = x[(size_t)(r0 + m) * 56 + d];
    }
    __syncthreads();
    float acc[TM];
#pragma unroll
    for (int m = 0; m < TM; m++) acc[m] = 0.f;
    for (int k = 0; k < 56; k++) {
        float wv = W[k * 128 + t];
#pragma unroll
        for (int m = 0; m < TM; m++) acc[m] = fmaf(xs[m][k], wv, acc[m]);
    }
#pragma unroll
    for (int m = 0; m < TM; m++) out[(size_t)(r0 + m) * 128 + t] = acc[m];
}

// ---------------- h = x@W + Wb ; hA = h@A  (merged, packed f32x2) ------------
template <int TM>   // TM must be even
__global__ void __launch_bounds__(128)
k_h_hA(const float* __restrict__ x1, const float* __restrict__ x2,
       const float* __restrict__ W, const float* __restrict__ Wb,
       const float* __restrict__ A,
       float* __restrict__ h1o, float* __restrict__ hA1o,
       float* __restrict__ h2o, float* __restrict__ hA2o) {
    constexpr int T1 = (B * N1) / TM;
    int blk = blockIdx.x;
    const float* x; float *ho, *hAo; int r0;
    if (blk < T1) { x = x1; ho = h1o; hAo = hA1o; r0 = blk * TM; }
    else          { x = x2; ho = h2o; hAo = hA2o; r0 = (blk - T1) * TM; }
    int t = threadIdx.x;
    __shared__ float xsT[128][TM + 2];
    __shared__ float hsT[128][TM + 2];
#pragma unroll
    for (int m = 0; m < TM; m++) xsT[t][m] = x[(size_t)(r0 + m) * 128 + t];
    __syncthreads();
    unsigned long long acc[TM / 2];
    float wb = Wb[t];
#pragma unroll
    for (int p = 0; p < TM / 2; p++) acc[p] = pack2(wb, wb);
    for (int k = 0; k < 128; k++) {
        float wv = W[k * 128 + t];
        unsigned long long w2 = pack2(wv, wv);
#pragma unroll
        for (int p = 0; p < TM / 2; p++) fma2(acc[p], lds2(&xsT[k][2 * p]), w2);
    }
#pragma unroll
    for (int p = 0; p < TM / 2; p++) {
        float lo, hi; unpack2(acc[p], lo, hi);
        ho[(size_t)(r0 + 2 * p) * 128 + t] = lo;
        ho[(size_t)(r0 + 2 * p + 1) * 128 + t] = hi;
        hsT[t][2 * p] = lo; hsT[t][2 * p + 1] = hi;
    }
    __syncthreads();
#pragma unroll
    for (int p = 0; p < TM / 2; p++) acc[p] = 0ull;
    for (int k = 0; k < 128; k++) {
        float av = A[k * 128 + t];
        unsigned long long a2 = pack2(av, av);
#pragma unroll
        for (int p = 0; p < TM / 2; p++) fma2(acc[p], lds2(&hsT[k][2 * p]), a2);
    }
#pragma unroll
    for (int p = 0; p < TM / 2; p++) {
        float lo, hi; unpack2(acc[p], lo, hi);
        hAo[(size_t)(r0 + 2 * p) * 128 + t] = lo;
        hAo[(size_t)(r0 + 2 * p + 1) * 128 + t] = hi;
    }
}

// ---- E = mask([hA,h] @ [h,hA]^T) : symmetric GEMM, upper-tri tiles only -----
// Epilogue also emits per-tile masked column stats (online max/sumexp) for
// both the direct and mirror writes.
constexpr int ET = 64;
__global__ void __launch_bounds__(256)
k_Egemm(const float* __restrict__ hA2, const float* __restrict__ h2,
        const float* __restrict__ adj2, float* __restrict__ E2,
        float* __restrict__ Mp2, float* __restrict__ Sp2,
        const float* __restrict__ hA1, const float* __restrict__ h1,
        const float* __restrict__ adj1, float* __restrict__ E1,
        float* __restrict__ Mp1, float* __restrict__ Sp1) {
    int blk = blockIdx.x;
    const float *hA, *hh, *adj; float *E, *Mp, *Sp; int N, b, tj, tk, TILES;
    if (blk < 288) {                 // 8 batches x 36 upper-tri tile pairs
        N = 512; b = blk / 36; TILES = 8;
        int tp = blk % 36;
        tj = 0;
        while (tp >= 8 - tj) { tp -= 8 - tj; tj++; }
        tk = tj + tp;
        hA = hA2; hh = h2; adj = adj2; E = E2; Mp = Mp2; Sp = Sp2;
    } else {                          // 8 batches x 1 tile (N1=64)
        N = 64; b = blk - 288; tj = 0; tk = 0; TILES = 1;
        hA = hA1; hh = h1; adj = adj1; E = E1; Mp = Mp1; Sp = Sp1;
    }
    int j0 = tj * ET, k0 = tk * ET;
    int t = threadIdx.x, tx = t & 15, ty = t >> 4;
    __shared__ float As[16][ET + 4];     // stride 68: float4-safe
    __shared__ float Bs[16][ET + 4];
    __shared__ float Es[ET][ET + 1];
    __shared__ float cm[4][66], cs[4][66];
    unsigned long long acc[2][4];
#pragma unroll
    for (int p = 0; p < 2; p++)
#pragma unroll
        for (int q = 0; q < 4; q++) acc[p][q] = 0ull;

    const float* A_hA = hA + ((size_t)b * N + j0) * 128;
    const float* A_h  = hh + ((size_t)b * N + j0) * 128;
    const float* B_h  = hh + ((size_t)b * N + k0) * 128;
    const float* B_hA = hA + ((size_t)b * N + k0) * 128;
    int lrow = t >> 2, ldq = t & 3;

    for (int dc = 0; dc < 256; dc += 16) {
        const float* sA = (dc < 128) ? (A_hA + dc) : (A_h + dc - 128);
        const float* sB = (dc < 128) ? (B_h + dc) : (B_hA + dc - 128);
        float4 va = *reinterpret_cast<const float4*>(&sA[(size_t)lrow * 128 + ldq * 4]);
        float4 vb = *reinterpret_cast<const float4*>(&sB[(size_t)lrow * 128 + ldq * 4]);
        __syncthreads();
        As[ldq * 4 + 0][lrow] = va.x; As[ldq * 4 + 1][lrow] = va.y;
        As[ldq * 4 + 2][lrow] = va.z; As[ldq * 4 + 3][lrow] = va.w;
        Bs[ldq * 4 + 0][lrow] = vb.x; Bs[ldq * 4 + 1][lrow] = vb.y;
        Bs[ldq * 4 + 2][lrow] = vb.z; Bs[ldq * 4 + 3][lrow] = vb.w;
        __syncthreads();
#pragma unroll
        for (int d = 0; d < 16; d++) {
            unsigned long long a2[2];
            a2[0] = lds2(&As[d][ty * 4]);
            a2[1] = lds2(&As[d][ty * 4 + 2]);
            float4 bv = *reinterpret_cast<const float4*>(&Bs[d][tx * 4]);
            unsigned long long b2[4] = {pack2(bv.x, bv.x), pack2(bv.y, bv.y),
                                        pack2(bv.z, bv.z), pack2(bv.w, bv.w)};
#pragma unroll
            for (int p = 0; p < 2; p++)
#pragma unroll
                for (int q = 0; q < 4; q++) fma2(acc[p][q], a2[p], b2[q]);
        }
    }
    __syncthreads();
#pragma unroll
    for (int p = 0; p < 2; p++)
#pragma unroll
        for (int q = 0; q < 4; q++) {
            float lo, hi; unpack2(acc[p][q], lo, hi);
            Es[ty * 4 + 2 * p][tx * 4 + q] = lo;
            Es[ty * 4 + 2 * p + 1][tx * 4 + q] = hi;
        }
    __syncthreads();
    size_t bNN = (size_t)b * N * N;
    int c = t & 63, quarter = t >> 6;
    // direct side: column k0+c, rows j0 + quarter+4i
    {
        float m = -INFINITY, s = 0.f;
#pragma unroll
        for (int i = 0; i < 16; i++) {
            int r = quarter + 4 * i;
            size_t off = bNN + (size_t)(j0 + r) * N + k0 + c;
            float a = adj[off];
            float v = (a > 0.f) ? Es[r][c] : -1e30f;
            E[off] = v;
            float mn = fmaxf(m, v);
            s = s * expf(m - mn) + expf(v - mn);
            m = mn;
        }
        cm[quarter][c] = m; cs[quarter][c] = s;
    }
    __syncthreads();
    if (t < 64) {
        float M = cm[0][t];
#pragma unroll
        for (int r = 1; r < 4; r++) M = fmaxf(M, cm[r][t]);
        float S = 0.f;
#pragma unroll
        for (int r = 0; r < 4; r++) S += cs[r][t] * expf(cm[r][t] - M);
        Mp[((size_t)b * TILES + tj) * N + k0 + t] = M;
        Sp[((size_t)b * TILES + tj) * N + k0 + t] = S;
    }
    if (tj != tk) {
        __syncthreads();
        // mirror side: column j0+c, rows k0 + quarter+4i
        float m = -INFINITY, s = 0.f;
#pragma unroll
        for (int i = 0; i < 16; i++) {
            int r = quarter + 4 * i;
            size_t off = bNN + (size_t)(k0 + r) * N + j0 + c;
            float a = adj[off];
            float v = (a > 0.f) ? Es[c][r] : -1e30f;
            E[off] = v;
            float mn = fmaxf(m, v);
            s = s * expf(m - mn) + expf(v - mn);
            m = mn;
        }
        cm[quarter][c] = m; cs[quarter][c] = s;
        __syncthreads();
        if (t < 64) {
            float M = cm[0][t];
#pragma unroll
            for (int r = 1; r < 4; r++) M = fmaxf(M, cm[r][t]);
            float S = 0.f;
#pragma unroll
            for (int r = 0; r < 4; r++) S += cs[r][t] * expf(cm[r][t] - M);
            Mp[((size_t)b * TILES + tk) * N + j0 + t] = M;
            Sp[((size_t)b * TILES + tk) * N + j0 + t] = S;
        }
    }
}

// ---- combine per-tile stats: M_k, invS_k per column -------------------------
__global__ void __launch_bounds__(256)
k_colstats2(const float* __restrict__ Mp2, const float* __restrict__ Sp2,
            float* __restrict__ M2o, float* __restrict__ S2o,
            const float* __restrict__ Mp1, const float* __restrict__ Sp1,
            float* __restrict__ M1o, float* __restrict__ S1o) {
    int idx = blockIdx.x * 256 + threadIdx.x;
    if (idx < B * N2) {
        int b = idx >> 9, k = idx & 511;
        float M = Mp2[((size_t)b * 8) * 512 + k];
        float S = Sp2[((size_t)b * 8) * 512 + k];
        for (int tile = 1; tile < 8; tile++) {
            float m = Mp2[((size_t)b * 8 + tile) * 512 + k];
            float s = Sp2[((size_t)b * 8 + tile) * 512 + k];
            float Mn = fmaxf(M, m);
            S = S * expf(M - Mn) + s * expf(m - Mn);
            M = Mn;
        }
        M2o[idx] = M; S2o[idx] = 1.f / S;
    } else {
        int i1 = idx - B * N2;
        if (i1 < B * N1) { M1o[i1] = Mp1[i1]; S1o[i1] = 1.f / Sp1[i1]; }
    }
}

// ---- hp = relu(att@h) ; gate : register-tiled GEMM, att built on the fly ----
// Block: 32 rows x 128 cols, 128 threads; thread = 4 row-pairs x 4 cols.
// att staged in 256-j chunks (stride-34 rows: 8B-aligned lds2).
constexpr int TMH = 32;
constexpr int JCH = 256;
__global__ void __launch_bounds__(128)
k_hp_gate(const float* __restrict__ x2, const float* __restrict__ h2,
          const float* __restrict__ E2, const float* __restrict__ M2, const float* __restrict__ S2,
          const float* __restrict__ x1, const float* __restrict__ h1,
          const float* __restrict__ E1, const float* __restrict__ M1, const float* __restrict__ S1,
          const float* __restrict__ Wg, const float* __restrict__ bg,
          float* __restrict__ o2, float* __restrict__ o1) {
    __shared__ float pool[JCH * 34];         // 34 KB; reused for hp tile [32][132]
    __shared__ float partial[TMH][4];
    __shared__ float coeff[TMH];
    int blk = blockIdx.x;
    const float *x, *hh, *E, *Mst, *Sst; float* out; int N, b, r0;
    if (blk < 128) { N = 512; b = blk >> 4; r0 = (blk & 15) * TMH;
                     x = x2; hh = h2; E = E2; Mst = M2; Sst = S2; out = o2; }
    else { int r = blk - 128; N = 64; b = r >> 1; r0 = (r & 1) * TMH;
           x = x1; hh = h1; E = E1; Mst = M1; Sst = S1; out = o1; }
    int t = threadIdx.x, tx = t & 31, ty = t >> 5;   // ty = row-group (8 rows)
    size_t bN = (size_t)b * N;
    unsigned long long acc[4][4];
#pragma unroll
    for (int p = 0; p < 4; p++)
#pragma unroll
        for (int q = 0; q < 4; q++) acc[p][q] = 0ull;

    for (int jc = 0; jc < N; jc += JCH) {
        int CH = (N - jc < JCH) ? (N - jc) : JCH;     // 256 or 64 (pow2)
        __syncthreads();
        // stage att chunk: pool[j*34 + m] = exp(E[r0+m][jc+j]-M)*invS
        int total = CH * TMH;
        for (int idx = t; idx < total; idx += 128) {
            int j = idx & (CH - 1);
            int m = (CH == 256) ? (idx >> 8) : (idx >> 6);
            float Mj = Mst[bN + jc + j], Sj = Sst[bN + jc + j];
            pool[j * 34 + m] = expf(E[(bN + r0 + m) * N + jc + j] - Mj) * Sj;
        }
        __syncthreads();
        for (int j = 0; j < CH; j++) {
            float4 hv = *reinterpret_cast<const float4*>(&hh[(bN + jc + j) * 128 + tx * 4]);
            unsigned long long b2[4] = {pack2(hv.x, hv.x), pack2(hv.y, hv.y),
                                        pack2(hv.z, hv.z), pack2(hv.w, hv.w)};
            const float* arow = &pool[j * 34 + ty * 8];
            unsigned long long a2[4];
            a2[0] = lds2(arow); a2[1] = lds2(arow + 2);
            a2[2] = lds2(arow + 4); a2[3] = lds2(arow + 6);
#pragma unroll
            for (int p = 0; p < 4; p++)
#pragma unroll
                for (int q = 0; q < 4; q++) fma2(acc[p][q], a2[p], b2[q]);
        }
    }
    __syncthreads();
    // write relu(hp) tile into pool as hps[r][c], stride 132
#pragma unroll
    for (int p = 0; p < 4; p++) {
        float lo[4], hi[4];
#pragma unroll
        for (int q = 0; q < 4; q++) {
            unpack2(acc[p][q], lo[q], hi[q]);
            lo[q] = fmaxf(lo[q], 0.f); hi[q] = fmaxf(hi[q], 0.f);
        }
        int rlo = ty * 8 + 2 * p, rhi = rlo + 1;
        *reinterpret_cast<float4*>(&pool[rlo * 132 + tx * 4]) =
            make_float4(lo[0], lo[1], lo[2], lo[3]);
        *reinterpret_cast<float4*>(&pool[rhi * 132 + tx * 4]) =
            make_float4(hi[0], hi[1], hi[2], hi[3]);
    }
    __syncthreads();
    // gate: thread t = column c
    int lane = t & 31, w = t >> 5;
    float wg0 = Wg[t], wg1 = Wg[128 + t];
    float xr[TMH];
#pragma unroll
    for (int m = 0; m < TMH; m++) {
        xr[m] = x[(bN + r0 + m) * 128 + t];
        float v = xr[m] * wg0 + pool[m * 132 + t] * wg1;
#pragma unroll
        for (int o = 16; o; o >>= 1) v += __shfl_down_sync(~0u, v, o);
        if (lane == 0) partial[m][w] = v;
    }
    __syncthreads();
    if (t < TMH)
        coeff[t] = sigmoidf(partial[t][0] + partial[t][1] + partial[t][2] + partial[t][3] + bg[0]);
    __syncthreads();
#pragma unroll
    for (int m = 0; m < TMH; m++) {
        float cc = coeff[m];
        out[(bN + r0 + m) * 128 + t] = cc * xr[m] + (1.f - cc) * pool[m * 132 + t];
    }
}

// ---------------- U precompute (merged, packed f32x2, TM=32) -----------------
constexpr int TMU = 32;
__global__ void __launch_bounds__(128)
k_precU(const float* __restrict__ x1e, const float* __restrict__ x2e,
        const float* __restrict__ WA1, const float* __restrict__ bA1,
        const float* __restrict__ WB1, const float* __restrict__ bB1,
        float* __restrict__ U1A, float* __restrict__ U1B,
        float* __restrict__ U2A, float* __restrict__ U2B) {
    constexpr int T1 = (B * N1) / TMU;      // 16
    int i = blockIdx.x % 7;
    int tile = blockIdx.x / 7;
    const float* x; float *UA, *UB; int r0, dOff; float biasMul;
    if (tile < T1) { x = x1e; UA = U1A; UB = U1B; r0 = tile * TMU; dOff = 0; biasMul = 1.f; }
    else { x = x2e; UA = U2A; UB = U2B; r0 = (tile - T1) * TMU; dOff = 128; biasMul = 0.f; }
    int hh = threadIdx.x;
    __shared__ float xsT[128][TMU + 2];
#pragma unroll
    for (int m = 0; m < TMU; m++) xsT[hh][m] = x[(size_t)(r0 + m) * 128 + hh];
    __syncthreads();
    float ba = bA1[i * 128 + hh] * biasMul, bb = bB1[i * 128 + hh] * biasMul;
    unsigned long long accA[TMU / 2], accB[TMU / 2];
#pragma unroll
    for (int p = 0; p < TMU / 2; p++) { accA[p] = pack2(ba, ba); accB[p] = pack2(bb, bb); }
    const float* wa = WA1 + ((size_t)i * 256 + dOff) * 128;
    const float* wb = WB1 + ((size_t)i * 256 + dOff) * 128;
    for (int d = 0; d < 128; d++) {
        float wav = wa[(size_t)d * 128 + hh], wbv = wb[(size_t)d * 128 + hh];
        unsigned long long w2a = pack2(wav, wav), w2b = pack2(wbv, wbv);
#pragma unroll
        for (int p = 0; p < TMU / 2; p++) {
            unsigned long long xs2 = lds2(&xsT[d][2 * p]);
            fma2(accA[p], xs2, w2a);
            fma2(accB[p], xs2, w2b);
        }
    }
#pragma unroll
    for (int p = 0; p < TMU / 2; p++) {
        float lo, hi;
        unpack2(accA[p], lo, hi);
        UA[((size_t)(r0 + 2 * p) * NT + i) * 128 + hh] = lo;
        UA[((size_t)(r0 + 2 * p + 1) * NT + i) * 128 + hh] = hi;
        unpack2(accB[p], lo, hi);
        UB[((size_t)(r0 + 2 * p) * NT + i) * 128 + hh] = lo;
        UB[((size_t)(r0 + 2 * p + 1) * NT + i) * 128 + hh] = hi;
    }
}

// ---------------- intercept ---------------------------------------------------
__global__ void k_intercept(const float* __restrict__ h1e, const float* __restrict__ valid,
                            const float* __restrict__ Wi1, const float* __restrict__ bi1,
                            const float* __restrict__ Wi2, const float* __restrict__ bi2,
                            float* __restrict__ out) {
    int b = blockIdx.x, t = threadIdx.x;
    int lane = t & 31, w = t >> 5;
    __shared__ float pooled[128];
    __shared__ float red[4];
    float p = 0.f;
    for (int j = 0; j < N1; j++)
        p = fmaf(h1e[((size_t)b * N1 + j) * 128 + t], valid[b * N1 + j], p);
    pooled[t] = p;
    __syncthreads();
    float acc = bi1[t];
    for (int d = 0; d < 128; d++) acc = fmaf(pooled[d], Wi1[d * 128 + t], acc);
    float v = fmaxf(acc, 0.f) * Wi2[t];
#pragma unroll
    for (int o = 16; o; o >>= 1) v += __shfl_down_sync(~0u, v, o);
    if (lane == 0) red[w] = v;
    __syncthreads();
    if (t == 0) {
        float s = red[0] + red[1] + red[2] + red[3] + bi2[0];
        s = 4.f * sigmoidf(s);
        float val = s / 7.f;
        for (int i = 0; i < NT; i++) out[b * NT + i] = val;
    }
}

// ---------------- sparse energies (dm computed inline from dmv) ---------------
__global__ void k_energy(const float* __restrict__ U1A, const float* __restrict__ U1B,
                         const float* __restrict__ U2A, const float* __restrict__ U2B,
                         const float* __restrict__ WA2, const float* __restrict__ bA2,
                         const float* __restrict__ WB2, const float* __restrict__ bB2,
                         const float* __restrict__ Cc, const float* __restrict__ A_int,
                         const float* __restrict__ dmv, float* __restrict__ epart) {
    int j = blockIdx.x % N1;
    int bi = blockIdx.x / N1;
    int i = bi % NT;
    int b = bi / NT;
    int t = threadIdx.x, lane = t & 31, w = t >> 5;
    __shared__ float u1a[128], u1b[128], wa2[128], wb2[128];
    __shared__ float part[4];
    u1a[t] = U1A[(((size_t)b * N1 + j) * NT + i) * 128 + t];
    u1b[t] = U1B[(((size_t)b * N1 + j) * NT + i) * 128 + t];
    wa2[t] = WA2[i * 128 + t];
    wb2[t] = WB2[i * 128 + t];
    __syncthreads();
    float bc = c_bconstraint[i];
    float bcinv = 1.f / (3.f * bc * bc);
    float Ci = Cc[i], ba2 = bA2[i], bb2 = bB2[i];
    const float* aint_row = A_int + (((size_t)b * NT + i) * N1 + j) * N2;
    const float* dmv_row = dmv + ((size_t)b * N1 + j) * N2 * 3;
    float esum = 0.f;
    for (int k = w; k < N2; k += 4) {
        float av = aint_row[k];
        if (av != 0.f) {
            const float* u2a = U2A + (((size_t)b * N2 + k) * NT + i) * 128;
            const float* u2b = U2B + (((size_t)b * N2 + k) * NT + i) * 128;
            float sA = 0.f, sB = 0.f;
#pragma unroll
            for (int q = 0; q < 4; q++) {
                int d = lane + 32 * q;
                sA = fmaf(fmaxf(u1a[d] + u2a[d], 0.f), wa2[d], sA);
                sB = fmaf(fmaxf(u1b[d] + u2b[d], 0.f), wb2[d], sB);
            }
#pragma unroll
            for (int o = 16; o; o >>= 1) {
                sA += __shfl_xor_sync(~0u, sA, o);
                sB += __shfl_xor_sync(~0u, sB, o);
            }
            if (lane == 0) {
                float xx = dmv_row[3 * k + 0];
                float yy = dmv_row[3 * k + 1];
                float zz = dmv_row[3 * k + 2];
                float dmval = sqrtf(xx * xx + yy * yy + zz * zz + 1e-10f);
                dmval = (dmval < 0.5f) ? 1e10f : dmval;
                float Aa = 4.f * sigmoidf(sA + ba2);
                float Bp = sigmoidf(sB + bb2) * (2.f * bcinv) + bcinv;
                float dd = dmval - Ci;
                esum += Aa * (Bp * dd * dd - 1.f) * av;
            }
        }
    }
    if (lane == 0) part[w] = esum;
    __syncthreads();
    if (t == 0) epart[blockIdx.x] = part[0] + part[1] + part[2] + part[3];
}

// ---------------- deterministic reduce ----------------------------------------
__global__ void k_reduce(const float* __restrict__ epart, float* __restrict__ out) {
    int t = threadIdx.x;
    if (t < B * NT) {
        float s = 0.f;
        for (int j = 0; j < N1; j++) s += epart[(size_t)t * N1 + j];
        out[t] += s;
    }
}

// ---------------- orchestration ------------------------------------------------
extern "C" void kernel_launch(void* const* d_in, const int* in_sizes, int n_in,
                              void* d_out, int out_size) {
    const float* h1     = (const float*)d_in[0];
    const float* adj1   = (const float*)d_in[1];
    const float* h2     = (const float*)d_in[2];
    const float* adj2   = (const float*)d_in[3];
    const float* A_int  = (const float*)d_in[4];
    const float* dmv    = (const float*)d_in[5];
    const float* valid  = (const float*)d_in[6];
    const float* W_embed= (const float*)d_in[7];
    const float* gW     = (const float*)d_in[8];
    const float* gWb    = (const float*)d_in[9];
    const float* gA     = (const float*)d_in[10];
    const float* gGateW = (const float*)d_in[11];
    const float* gGateb = (const float*)d_in[12];
    const float* WA1    = (const float*)d_in[13];
    const float* bA1    = (const float*)d_in[14];
    const float* WA2    = (const float*)d_in[15];
    const float* bA2    = (const float*)d_in[16];
    const float* WB1    = (const float*)d_in[17];
    const float* bB1    = (const float*)d_in[18];
    const float* WB2    = (const float*)d_in[19];
    const float* bB2    = (const float*)d_in[20];
    const float* Cc     = (const float*)d_in[21];
    const float* Wi1    = (const float*)d_in[22];
    const float* bi1    = (const float*)d_in[23];
    const float* Wi2    = (const float*)d_in[24];
    const float* bi2    = (const float*)d_in[25];
    float* out = (float*)d_out;

    float* S = nullptr;
    cudaGetSymbolAddress((void**)&S, g_scratch);

    float* h1buf[2] = {S + OFF_H1A, S + OFF_H1B};
    float* h2buf[2] = {S + OFF_H2A, S + OFF_H2B};
    float* t1   = S + OFF_T1;
    float* ta1  = S + OFF_TA1;
    float* t2   = S + OFF_T2;
    float* ta2  = S + OFF_TA2;
    float* E1   = S + OFF_E1;
    float* E2   = S + OFF_E2;
    float* M1   = S + OFF_M1;
    float* S1b  = S + OFF_S1;
    float* M2   = S + OFF_M2;
    float* S2b  = S + OFF_S2;
    float* Mp2  = S + OFF_MP2;
    float* Sp2  = S + OFF_SP2;
    float* Mp1  = S + OFF_MP1;
    float* Sp1  = S + OFF_SP1;
    float* U1A  = S + OFF_U1A;
    float* U1B  = S + OFF_U1B;
    float* U2A  = S + OFF_U2A;
    float* U2B  = S + OFF_U2B;
    float* ep   = S + OFF_EP;

    // 1. embed (merged)
    k_embed<8><<<(B * N1 + B * N2) / 8, 128>>>(h1, h2, W_embed, h1buf[0], h2buf[0]);

    // 2. GAT layers (graph1 + graph2 merged per stage)
    int cur = 0;
    for (int l = 0; l < NL; l++) {
        const float* W  = gW + (size_t)l * D * D;
        const float* Wb = gWb + (size_t)l * D;
        const float* A  = gA + (size_t)l * D * D;
        const float* Gw = gGateW + (size_t)l * 2 * D;
        const float* Gb = gGateb + l;
        int nxt = cur ^ 1;
        k_h_hA<8><<<(B * N1 + B * N2) / 8, 128>>>(h1buf[cur], h2buf[cur], W, Wb, A,
                                                  t1, ta1, t2, ta2);
        k_Egemm<<<288 + 8, 256>>>(ta2, t2, adj2, E2, Mp2, Sp2,
                                  ta1, t1, adj1, E1, Mp1, Sp1);
        k_colstats2<<<(B * N2 + B * N1 + 255) / 256, 256>>>(Mp2, Sp2, M2, S2b,
                                                            Mp1, Sp1, M1, S1b);
        k_hp_gate<<<128 + 16, 128>>>(h2buf[cur], t2, E2, M2, S2b,
                                     h1buf[cur], t1, E1, M1, S1b,
                                     Gw, Gb, h2buf[nxt], h1buf[nxt]);
        cur = nxt;
    }
    const float* h1e = h1buf[cur];
    const float* h2e = h2buf[cur];

    // 3. factored MLP first layer (merged)
    k_precU<<<7 * ((B * N1 + B * N2) / TMU), 128>>>(h1e, h2e, WA1, bA1, WB1, bB1,
                                                    U1A, U1B, U2A, U2B);

    // 4. intercept (initializes out), sparse energies (dm inline), reduce
    k_intercept<<<B, 128>>>(h1e, valid, Wi1, bi1, Wi2, bi2, out);
    k_energy<<<B * NT * N1, 128>>>(U1A, U1B, U2A, U2B, WA2, bA2, WB2, bB2,
                                   Cc, A_int, dmv, ep);
    k_reduce<<<1, 64>>>(ep, out);
}